// round 10
// baseline (speedup 1.0000x reference)
#include <cuda_runtime.h>
#include <math_constants.h>
#include <cstdint>

#define BB 8
#define SS_ 1024
#define D0 128
#define DD 256
#define HH 8
#define HD 32
#define BH (BB*HH)     // 64
#define BSr (BB*SS_)   // 8192
#define LOG2E 1.4426950408889634f

// ---------------- scratch ---------------------------------------------------
__device__ float g_Q [BH*SS_*HD];          // [bh][s][d]
__device__ float g_Kp[BH*HD*SS_];          // paired: [bh][d/2][s] float2
__device__ float g_Vt[BH*HD*SS_];          // [bh][d][s]
__device__ float g_maskadd[BH*SS_];        // 0 or -inf per (bh, key)
__device__ float g_AO[BSr*DD];             // pre-Wo context [bs][e]
__device__ float g_SF[(size_t)BH*SS_*SS_]; // fallback score buffer

// ---------------- packed f32x2 helpers -------------------------------------
__device__ __forceinline__ void ffma2(unsigned long long& d,
                                      unsigned long long a,
                                      unsigned long long b) {
    asm("fma.rn.f32x2 %0, %1, %2, %0;" : "+l"(d) : "l"(a), "l"(b));
}
__device__ __forceinline__ float f2sum(unsigned long long v) {
    float lo, hi;
    asm("mov.b64 {%0, %1}, %2;" : "=f"(lo), "=f"(hi) : "l"(v));
    return lo + hi;
}
__device__ __forceinline__ float ex2(float x) {
    float r;
    asm("ex2.approx.ftz.f32 %0, %1;" : "=f"(r) : "f"(x));
    return r;
}

// ---------------- K1: fused Q/K/V projection (+mask, +K/V transpose) --------
// grid (BSr/64, 4, 3). z=0 -> g_Q + maskadd; z=1 -> g_Kp; z=2 -> g_Vt.
__global__ __launch_bounds__(256, 3)
void gemmQKV(const float* __restrict__ A,
             const float* __restrict__ Wq, const float* __restrict__ Wk,
             const float* __restrict__ Wv)
{
    extern __shared__ float sm[];
    float* Xs  = sm;                // 64*128 = 8192 (reused as Cs 64x65)
    float* Wt2 = sm + 8192;         // 64 j x 65 f2 = 8320 floats

    const int tid = threadIdx.x;
    const int w = tid >> 5, lane = tid & 31;
    const int r0 = w * 8;
    const int row0 = blockIdx.x * 64;
    const int n0 = blockIdx.y * 64;
    const int z = blockIdx.z;
    const float* W = (z == 0) ? Wq : (z == 1) ? Wk : Wv;

    for (int idx = tid; idx < 64 * 128; idx += 256) {
        int r = idx >> 7, d = idx & 127;
        Xs[r * 128 + d] = A[(size_t)(row0 + r) * D0 + d];
    }
#pragma unroll
    for (int t = 0; t < 16; t++) {
        int i = tid + t * 256;              // < 4096
        int j = i & 63, e = i >> 6;
        *reinterpret_cast<unsigned long long*>(&Wt2[(j * 65 + e) * 2]) =
            *reinterpret_cast<const unsigned long long*>(&W[(size_t)(n0 + e) * D0 + 2 * j]);
    }
    __syncthreads();

    unsigned long long acc[8][2];
#pragma unroll
    for (int r = 0; r < 8; r++)
#pragma unroll
        for (int c = 0; c < 2; c++) acc[r][c] = 0ull;

#pragma unroll 8
    for (int j = 0; j < 64; j++) {
        unsigned long long qa[8];
#pragma unroll
        for (int r = 0; r < 8; r++)
            qa[r] = *reinterpret_cast<const unsigned long long*>(
                        &Xs[(r0 + r) * 128 + 2 * j]);
#pragma unroll
        for (int c = 0; c < 2; c++) {
            unsigned long long b2 = *reinterpret_cast<const unsigned long long*>(
                        &Wt2[(j * 65 + lane + 32 * c) * 2]);
#pragma unroll
            for (int r = 0; r < 8; r++) ffma2(acc[r][c], qa[r], b2);
        }
    }

    if (z == 0) {
        int b = row0 >> 10;
#pragma unroll
        for (int r = 0; r < 8; r++) {
            int s = (row0 + r0 + r) & 1023;
#pragma unroll
            for (int c = 0; c < 2; c++) {
                float y = f2sum(acc[r][c]);
                int e = n0 + lane + 32 * c;
                int h = e >> 5, d = e & 31;
                g_Q[(((size_t)(b * HH + h)) * SS_ + s) * HD + d] = y;
                float hs = y;
#pragma unroll
                for (int off = 16; off; off >>= 1)
                    hs += __shfl_xor_sync(0xffffffffu, hs, off);
                if (lane == 0)
                    g_maskadd[(b * HH + h) * SS_ + s] = (hs != 0.0f) ? 0.0f : -CUDART_INF_F;
            }
        }
    } else {
        __syncthreads();
        float* Cs = Xs;   // 64 x 65
#pragma unroll
        for (int r = 0; r < 8; r++)
#pragma unroll
            for (int c = 0; c < 2; c++)
                Cs[(r0 + r) * 65 + lane + 32 * c] = f2sum(acc[r][c]);
        __syncthreads();
        int b = row0 >> 10;
        if (z == 1) {
#pragma unroll
            for (int t = 0; t < 4; t++) {
                int i = tid + t * 256;          // < 1024
                int pr = i >> 5, sp = i & 31;
                int eL = 2 * pr;
                int e0 = n0 + eL;
                int h = e0 >> 5, j = (e0 & 31) >> 1;
                float4 v = make_float4(Cs[(2 * sp) * 65 + eL],
                                       Cs[(2 * sp) * 65 + eL + 1],
                                       Cs[(2 * sp + 1) * 65 + eL],
                                       Cs[(2 * sp + 1) * 65 + eL + 1]);
                int s0 = (row0 & 1023) + 2 * sp;
                *reinterpret_cast<float4*>(
                    &g_Kp[((((size_t)(b * HH + h)) * 16 + j) * SS_ + s0) * 2]) = v;
            }
        } else {
#pragma unroll
            for (int t = 0; t < 4; t++) {
                int i = tid + t * 256;          // < 1024
                int e = i >> 4, sq = i & 15;
                float4 v = make_float4(Cs[(4 * sq + 0) * 65 + e],
                                       Cs[(4 * sq + 1) * 65 + e],
                                       Cs[(4 * sq + 2) * 65 + e],
                                       Cs[(4 * sq + 3) * 65 + e]);
                int eg = n0 + e;
                int h = eg >> 5, d = eg & 31;
                *reinterpret_cast<float4*>(
                    &g_Vt[(((size_t)(b * HH + h)) * HD + d) * SS_ + (row0 & 1023) + 4 * sq]) = v;
            }
        }
    }
}

// ---------------- K2: output projection  out = g_AO[8192x256] * Wo^T --------
__global__ __launch_bounds__(256, 3)
void gemmO(const float* __restrict__ W, float* __restrict__ Oarg)
{
    extern __shared__ float sm[];
    float* Xs  = sm;                // 64*128
    float* Wt2 = sm + 8192;         // 64 x 65 f2

    const int tid = threadIdx.x;
    const int w = tid >> 5, lane = tid & 31;
    const int r0 = w * 8;
    const int row0 = blockIdx.x * 64;
    const int n0 = blockIdx.y * 64;

    unsigned long long acc[8][2];
#pragma unroll
    for (int r = 0; r < 8; r++)
#pragma unroll
        for (int c = 0; c < 2; c++) acc[r][c] = 0ull;

    for (int k0 = 0; k0 < DD; k0 += 128) {
        __syncthreads();
        for (int idx = tid; idx < 64 * 128; idx += 256) {
            int r = idx >> 7, d = idx & 127;
            Xs[r * 128 + d] = g_AO[(size_t)(row0 + r) * DD + k0 + d];
        }
#pragma unroll
        for (int t = 0; t < 16; t++) {
            int i = tid + t * 256;
            int j = i & 63, e = i >> 6;
            *reinterpret_cast<unsigned long long*>(&Wt2[(j * 65 + e) * 2]) =
                *reinterpret_cast<const unsigned long long*>(
                    &W[(size_t)(n0 + e) * DD + k0 + 2 * j]);
        }
        __syncthreads();
#pragma unroll 8
        for (int j = 0; j < 64; j++) {
            unsigned long long qa[8];
#pragma unroll
            for (int r = 0; r < 8; r++)
                qa[r] = *reinterpret_cast<const unsigned long long*>(
                            &Xs[(r0 + r) * 128 + 2 * j]);
#pragma unroll
            for (int c = 0; c < 2; c++) {
                unsigned long long b2 = *reinterpret_cast<const unsigned long long*>(
                            &Wt2[(j * 65 + lane + 32 * c) * 2]);
#pragma unroll
                for (int r = 0; r < 8; r++) ffma2(acc[r][c], qa[r], b2);
            }
        }
    }
#pragma unroll
    for (int r = 0; r < 8; r++)
#pragma unroll
        for (int c = 0; c < 2; c++)
            Oarg[(size_t)(row0 + r0 + r) * D0 + n0 + lane + 32 * c] = f2sum(acc[r][c]);
}

// ---------------- K3: fused attention (single-pass AV) ----------------------
// grid (S/64, BH), 256 thr, 2 CTAs/SM. Warp w owns rows 8w..8w+7.
// Per K-tile: stage K+V, QK -> e (regs) -> {gmem, Ps smem}, l += e, AV(Ps,V).
// End: inv = 1/l; streaming sweep normalizes the e-slab (L2-hot); oacc *= inv.
__global__ __launch_bounds__(256, 2)
void attn_kernel(const float* __restrict__ U, float* __restrict__ sattn)
{
    extern __shared__ float sm[];
    float* Qs    = sm;              // 64*32 = 2048
    float* msk   = sm + 2048;       // 1024
    float* inv_s = sm + 3072;       // 64 (+16 pad)
    float* Kt    = sm + 3152;       // 16 x 130 f2 = 4160
    float* Vt    = sm + 3152 + 4160;        // 32 x 130 = 4160
    float* Ps    = sm + 3152 + 8320;        // 64 x 132 = 8448
    // total 19920 floats = 79680 B

    const int tid = threadIdx.x, w = tid >> 5, lane = tid & 31;
    const int r0 = w * 8;
    const int bh = blockIdx.y;
    const int q0 = blockIdx.x * 64;
    const float inv_scale = 0.17677669529663687f;   // 1/sqrt(32)

    const float* gq  = g_Q  + (size_t)bh * SS_ * HD;
    const float* gkp = g_Kp + (size_t)bh * HD * SS_;
    const float* gvt = g_Vt + (size_t)bh * HD * SS_;
    float* srow = sattn + ((size_t)bh * SS_ + q0) * SS_;

    {   // stage Q tile (64x32) + mask
        const float4* q4 = reinterpret_cast<const float4*>(gq + (size_t)q0 * HD);
        reinterpret_cast<float4*>(Qs)[tid]       = q4[tid];
        reinterpret_cast<float4*>(Qs)[tid + 256] = q4[tid + 256];
        const float4* m4 = reinterpret_cast<const float4*>(g_maskadd + bh * SS_);
        reinterpret_cast<float4*>(msk)[tid] = m4[tid];
    }

    float l_loc[8];
    unsigned long long oacc[8];
#pragma unroll
    for (int r = 0; r < 8; r++) { l_loc[r] = 0.f; oacc[r] = 0ull; }

    for (int kb = 0; kb < SS_; kb += 128) {
        __syncthreads();    // Kt/Vt/Ps reuse-safe
        {   // stage paired K tile [j][k] f2 (pad 130) + V tile [d][k] (pad 130)
#pragma unroll
            for (int t = 0; t < 4; t++) {
                int i = tid + t * 256;      // < 1024
                int j = i >> 6, kq = i & 63;
                float4 v = *reinterpret_cast<const float4*>(
                               &gkp[((size_t)j * SS_ + kb + 2 * kq) * 2]);
                *reinterpret_cast<float4*>(&Kt[(j * 130 + 2 * kq) * 2]) = v;
            }
#pragma unroll
            for (int t = 0; t < 4; t++) {
                int i = tid + t * 256;
                int d = i >> 5, kq = i & 31;
                float4 v = *reinterpret_cast<const float4*>(
                               &gvt[(size_t)d * SS_ + kb + 4 * kq]);
                float* dst = &Vt[d * 130 + 4 * kq];
                *reinterpret_cast<float2*>(dst)     = make_float2(v.x, v.y);
                *reinterpret_cast<float2*>(dst + 2) = make_float2(v.z, v.w);
            }
        }
        __syncthreads();

        // ---- QK ----
        unsigned long long acc[8][4];
#pragma unroll
        for (int r = 0; r < 8; r++)
#pragma unroll
            for (int c = 0; c < 4; c++) acc[r][c] = 0ull;

#pragma unroll
        for (int j = 0; j < HD / 2; j++) {
            unsigned long long qa[8];
#pragma unroll
            for (int r = 0; r < 8; r++)
                qa[r] = *reinterpret_cast<const unsigned long long*>(
                            &Qs[(r0 + r) * HD + 2 * j]);
#pragma unroll
            for (int c = 0; c < 4; c++) {
                unsigned long long b2 = *reinterpret_cast<const unsigned long long*>(
                            &Kt[(j * 130 + lane + 32 * c) * 2]);
#pragma unroll
                for (int r = 0; r < 8; r++) ffma2(acc[r][c], qa[r], b2);
            }
        }

        // ---- epilogue: e = exp(score) -> gmem + Ps; l += e ----
#pragma unroll
        for (int r = 0; r < 8; r++) {
            const float* up = U + ((size_t)bh * SS_ + q0 + r0 + r) * SS_ + kb + lane;
            float* ep = srow + (size_t)(r0 + r) * SS_ + kb + lane;
            float lr = l_loc[r];
#pragma unroll
            for (int c = 0; c < 4; c++) {
                float s = (f2sum(acc[r][c]) + up[32 * c]) * inv_scale
                        + msk[kb + lane + 32 * c];
                float e = ex2(s * LOG2E);   // exp(s); -inf -> 0
                ep[32 * c] = e;
                Ps[(r0 + r) * 132 + lane + 32 * c] = e;
                lr += e;
            }
            l_loc[r] = lr;
        }
        __syncthreads();    // Ps complete

        // ---- AV on unnormalized e ----
#pragma unroll 4
        for (int k = 0; k < 128; k += 4) {
            unsigned long long v2a = *reinterpret_cast<const unsigned long long*>(
                    &Vt[lane * 130 + k]);
            unsigned long long v2b = *reinterpret_cast<const unsigned long long*>(
                    &Vt[lane * 130 + k + 2]);
#pragma unroll
            for (int r = 0; r < 8; r++) {
                unsigned long long pa = *reinterpret_cast<const unsigned long long*>(
                        &Ps[(r0 + r) * 132 + k]);
                unsigned long long pb = *reinterpret_cast<const unsigned long long*>(
                        &Ps[(r0 + r) * 132 + k + 2]);
                ffma2(oacc[r], pa, v2a);
                ffma2(oacc[r], pb, v2b);
            }
        }
    }

    // ---- l -> inv ----
#pragma unroll
    for (int r = 0; r < 8; r++) {
        float l = l_loc[r];
#pragma unroll
        for (int off = 16; off; off >>= 1)
            l += __shfl_xor_sync(0xffffffffu, l, off);
        if (lane == 0) inv_s[r0 + r] = 1.0f / l;
    }
    __syncthreads();

    // ---- streaming normalize sweep over the L2-hot e-slab ----
    {
        float4* s4 = reinterpret_cast<float4*>(srow);   // 64 rows x 256 f4
#pragma unroll 4
        for (int t = 0; t < 64; t++) {
            float iv = inv_s[t];
            float4 v = s4[t * 256 + tid];
            v.x *= iv; v.y *= iv; v.z *= iv; v.w *= iv;
            s4[t * 256 + tid] = v;
        }
    }

    // ---- AO store (scaled) ----
    {
        int b = bh >> 3, h = bh & 7;
#pragma unroll
        for (int r = 0; r < 8; r++) {
            int s = q0 + r0 + r;
            g_AO[((size_t)b * SS_ + s) * DD + h * HD + lane] =
                f2sum(oacc[r]) * inv_s[r0 + r];
        }
    }
}

// ---------------- launcher --------------------------------------------------
extern "C" void kernel_launch(void* const* d_in, const int* in_sizes, int n_in,
                              void* d_out, int out_size)
{
    const float* query = (const float*)d_in[0];
    const float* U     = (const float*)d_in[1];
    const float* Wq    = (const float*)d_in[2];
    const float* Wk    = (const float*)d_in[3];
    const float* Wv    = (const float*)d_in[4];
    const float* Wo    = (const float*)d_in[5];

    float* outp = (float*)d_out;
    const long long total = (long long)BSr * D0 + (long long)BH * SS_ * SS_;
    float* attnp = nullptr;
    if ((long long)out_size >= total) attnp = outp + (size_t)BSr * D0;

    float* sbuf = attnp;
    if (!sbuf) { cudaGetSymbolAddress((void**)&sbuf, g_SF); }

    const size_t gemm_smem = (size_t)(8192 + 8320) * sizeof(float);   // 66048 B
    const size_t attn_smem = (size_t)19920 * sizeof(float);           // 79680 B
    cudaFuncSetAttribute(gemmQKV, cudaFuncAttributeMaxDynamicSharedMemorySize, (int)gemm_smem);
    cudaFuncSetAttribute(gemmO, cudaFuncAttributeMaxDynamicSharedMemorySize, (int)gemm_smem);
    cudaFuncSetAttribute(attn_kernel, cudaFuncAttributeMaxDynamicSharedMemorySize, (int)attn_smem);

    gemmQKV<<<dim3(BSr / 64, 4, 3), 256, gemm_smem>>>(query, Wq, Wk, Wv);
    attn_kernel<<<dim3(SS_ / 64, BH), 256, attn_smem>>>(U, sbuf);
    gemmO<<<dim3(BSr / 64, 2), 256, gemm_smem>>>(Wo, outp);
}